// round 1
// baseline (speedup 1.0000x reference)
#include <cuda_runtime.h>
#include <math.h>

#define DIM   768
#define HEADS 12
#define HD    64
#define BS    32
#define NMM   256
#define NV    196
#define NA    60
#define NKV   256               // NV + NA
#define M_ROWS (BS * NMM)       // 8192

// Scratch (no cudaMalloc allowed): 96 MB of device globals.
__device__ float g_Q[BS * HEADS * NMM * HD];   // [b,h,q,d]
__device__ float g_K[BS * HEADS * NKV * HD];   // [b,h,k,d]
__device__ float g_V[BS * HEADS * NKV * HD];   // [b,h,k,d]
__device__ float g_O[M_ROWS * DIM];            // [b*q, h*d]

// ---------------------------------------------------------------------------
// Generic 128x128x8 fp32 GEMM, 256 threads, 8x8 per thread, fused epilogues.
// MODE 0: Q = xmm @ Wq            -> g_Q in [b,h,q,d]
// MODE 1: KV = concat(xv,xa) @ Wkv -> g_K/g_V in [b,h,t,d]
// MODE 2: out = g_O @ Wproj + bias -> C (row-major [8192,768])
// ---------------------------------------------------------------------------
template <int MODE>
__global__ __launch_bounds__(256, 2)
void gemm_kernel(const float* __restrict__ A, const float* __restrict__ A2,
                 const float* __restrict__ B, const float* __restrict__ bias,
                 float* __restrict__ C, int N)
{
    __shared__ float As[8][128];   // As[k][m] (transposed A tile)
    __shared__ float Bs[8][128];   // Bs[k][n]

    const int tid = threadIdx.x;
    const int m0  = blockIdx.y * 128;
    const int n0  = blockIdx.x * 128;

    // --- A tile loader mapping: each thread loads one float4 ---
    const int lrow = tid >> 1;          // 0..127 (tile row)
    const int lk   = (tid & 1) * 4;     // 0 or 4 (k offset)
    const int grow = m0 + lrow;
    const float* arow;
    if (MODE == 1) {
        const int b = grow >> 8;
        const int t = grow & 255;
        arow = (t < NV) ? (A  + (b * NV + t) * DIM)
                        : (A2 + (b * NA + (t - NV)) * DIM);
    } else if (MODE == 2) {
        arow = g_O + grow * DIM;
    } else {
        arow = A + grow * DIM;
    }

    // --- B tile loader mapping ---
    const int brow = tid >> 5;          // 0..7
    const int bcol = (tid & 31) * 4;    // 0..124

    // --- compute mapping: 4-spread (conflict-free float4 smem reads) ---
    const int ty = tid >> 4;            // 0..15 -> rows {ty*4..+3, 64+ty*4..+3}
    const int tx = tid & 15;            // 0..15 -> cols {tx*4..+3, 64+tx*4..+3}

    float acc[8][8];
#pragma unroll
    for (int i = 0; i < 8; i++)
#pragma unroll
        for (int j = 0; j < 8; j++) acc[i][j] = 0.f;

    for (int k0 = 0; k0 < DIM; k0 += 8) {
        const float4 av = *reinterpret_cast<const float4*>(arow + k0 + lk);
        const float4 bv = *reinterpret_cast<const float4*>(B + (k0 + brow) * N + n0 + bcol);
        __syncthreads();               // previous tile's compute done
        As[lk + 0][lrow] = av.x;
        As[lk + 1][lrow] = av.y;
        As[lk + 2][lrow] = av.z;
        As[lk + 3][lrow] = av.w;
        *reinterpret_cast<float4*>(&Bs[brow][bcol]) = bv;
        __syncthreads();               // tile visible

#pragma unroll
        for (int kk = 0; kk < 8; kk++) {
            float a[8], bb[8];
            *reinterpret_cast<float4*>(&a[0])  = *reinterpret_cast<const float4*>(&As[kk][ty * 4]);
            *reinterpret_cast<float4*>(&a[4])  = *reinterpret_cast<const float4*>(&As[kk][64 + ty * 4]);
            *reinterpret_cast<float4*>(&bb[0]) = *reinterpret_cast<const float4*>(&Bs[kk][tx * 4]);
            *reinterpret_cast<float4*>(&bb[4]) = *reinterpret_cast<const float4*>(&Bs[kk][64 + tx * 4]);
#pragma unroll
            for (int i = 0; i < 8; i++)
#pragma unroll
                for (int j = 0; j < 8; j++)
                    acc[i][j] += a[i] * bb[j];
        }
    }

    // --- epilogue (float4 stores) ---
#pragma unroll
    for (int i = 0; i < 8; i++) {
        const int r = m0 + ty * 4 + (i & 3) + (i >> 2) * 64;
#pragma unroll
        for (int jh = 0; jh < 2; jh++) {
            const int c0 = n0 + tx * 4 + jh * 64;
            float4 v = make_float4(acc[i][jh * 4 + 0], acc[i][jh * 4 + 1],
                                   acc[i][jh * 4 + 2], acc[i][jh * 4 + 3]);
            if (MODE == 0) {
                const int b = r >> 8, q = r & 255;
                const int h = c0 >> 6, d = c0 & 63;
                *reinterpret_cast<float4*>(&g_Q[((b * HEADS + h) * NMM + q) * HD + d]) = v;
            } else if (MODE == 1) {
                const int b = r >> 8, t = r & 255;
                const bool isv = (c0 >= DIM);
                const int cc = isv ? (c0 - DIM) : c0;
                const int h = cc >> 6, d = cc & 63;
                float* dst = isv ? g_V : g_K;
                *reinterpret_cast<float4*>(&dst[((b * HEADS + h) * NKV + t) * HD + d]) = v;
            } else {
                v.x += bias[c0 + 0];
                v.y += bias[c0 + 1];
                v.z += bias[c0 + 2];
                v.w += bias[c0 + 3];
                *reinterpret_cast<float4*>(&C[r * DIM + c0]) = v;
            }
        }
    }
}

// ---------------------------------------------------------------------------
// Attention: one CTA per (b,h). K,V in 128 KB smem; one thread per query.
// Pass 1: online softmax stats. Pass 2: recompute scores, write attn probs
// (float4) and accumulate O. Writes g_O in [b*q, h*d].
// ---------------------------------------------------------------------------
__global__ __launch_bounds__(256, 1)
void attn_kernel(float* __restrict__ attn)
{
    extern __shared__ float sh[];
    float* Ksh = sh;                 // NKV*HD = 16384 floats
    float* Vsh = sh + NKV * HD;      // 16384 floats

    const int bh  = blockIdx.x;      // b*HEADS + h
    const int b   = bh / HEADS;
    const int h   = bh - b * HEADS;
    const int tid = threadIdx.x;

    const float4* kg = reinterpret_cast<const float4*>(g_K + (size_t)bh * NKV * HD);
    const float4* vg = reinterpret_cast<const float4*>(g_V + (size_t)bh * NKV * HD);
    float4* k4 = reinterpret_cast<float4*>(Ksh);
    float4* v4 = reinterpret_cast<float4*>(Vsh);
#pragma unroll 4
    for (int i = tid; i < NKV * HD / 4; i += 256) {
        k4[i] = kg[i];
        v4[i] = vg[i];
    }
    __syncthreads();

    const int q = tid;               // 256 threads == 256 queries
    float qreg[HD];
    const float4* qg = reinterpret_cast<const float4*>(g_Q + ((size_t)bh * NMM + q) * HD);
#pragma unroll
    for (int i = 0; i < HD / 4; i++)
        *reinterpret_cast<float4*>(&qreg[4 * i]) = qg[i];

    const float scale = 0.125f;      // 1/sqrt(64)

    // Pass 1: running max + denominator
    float m = -INFINITY, l = 0.f;
    for (int k = 0; k < NKV; k++) {
        const float* kr = Ksh + k * HD;
        float s = 0.f;
#pragma unroll
        for (int d = 0; d < HD; d++) s += qreg[d] * kr[d];
        s *= scale;
        const float mn = fmaxf(m, s);
        l = l * __expf(m - mn) + __expf(s - mn);
        m = mn;
    }
    const float inv = 1.0f / l;

    // Pass 2: probs + AV accumulation
    float o[HD];
#pragma unroll
    for (int d = 0; d < HD; d++) o[d] = 0.f;

    float* arow = attn + ((size_t)bh * NMM + q) * NKV;
    for (int k = 0; k < NKV; k += 4) {
        float ps[4];
#pragma unroll
        for (int u = 0; u < 4; u++) {
            const float* kr = Ksh + (k + u) * HD;
            float s = 0.f;
#pragma unroll
            for (int d = 0; d < HD; d++) s += qreg[d] * kr[d];
            const float p = __expf(s * scale - m) * inv;
            ps[u] = p;
            const float* vr = Vsh + (k + u) * HD;
#pragma unroll
            for (int d = 0; d < HD; d++) o[d] += p * vr[d];
        }
        *reinterpret_cast<float4*>(arow + k) = make_float4(ps[0], ps[1], ps[2], ps[3]);
    }

    float* op = g_O + ((size_t)b * NMM + q) * DIM + h * HD;
#pragma unroll
    for (int i = 0; i < HD / 4; i++)
        reinterpret_cast<float4*>(op)[i] = *reinterpret_cast<const float4*>(&o[4 * i]);
}

// ---------------------------------------------------------------------------
extern "C" void kernel_launch(void* const* d_in, const int* in_sizes, int n_in,
                              void* d_out, int out_size)
{
    const float* xmm   = (const float*)d_in[0];
    const float* xv    = (const float*)d_in[1];
    const float* xa    = (const float*)d_in[2];
    const float* Wq    = (const float*)d_in[3];
    const float* Wkv   = (const float*)d_in[4];
    const float* Wproj = (const float*)d_in[5];
    const float* bproj = (const float*)d_in[6];

    float* out  = (float*)d_out;                 // [32,256,768]
    float* attn = out + (size_t)BS * NMM * DIM;  // [32,12,256,256]

    cudaFuncSetAttribute(attn_kernel, cudaFuncAttributeMaxDynamicSharedMemorySize,
                         2 * NKV * HD * (int)sizeof(float));

    gemm_kernel<0><<<dim3(DIM / 128, M_ROWS / 128), 256>>>(xmm, nullptr, Wq, nullptr, nullptr, DIM);
    gemm_kernel<1><<<dim3(2 * DIM / 128, M_ROWS / 128), 256>>>(xv, xa, Wkv, nullptr, nullptr, 2 * DIM);
    attn_kernel<<<BS * HEADS, 256, 2 * NKV * HD * (int)sizeof(float)>>>(attn);
    gemm_kernel<2><<<dim3(DIM / 128, M_ROWS / 128), 256>>>(nullptr, nullptr, Wproj, bproj, out, DIM);
}

// round 4
// speedup vs baseline: 1.7274x; 1.7274x over previous
#include <cuda_runtime.h>
#include <cuda_bf16.h>
#include <math.h>
#include <stdint.h>

#define DIM   768
#define HEADS 12
#define HD    64
#define BS    32
#define NMM   256
#define NV    196
#define NA    60
#define NKV   256
#define M_ROWS (BS * NMM)       // 8192

// ---------------- scratch (device globals; no cudaMalloc allowed) ----------
__device__ float g_Q[BS * HEADS * NMM * HD];   // [b,h,q,d]
__device__ float g_K[BS * HEADS * NKV * HD];
__device__ float g_V[BS * HEADS * NKV * HD];
__device__ float g_O[M_ROWS * DIM];            // [b*q, h*d]

__device__ __align__(16) __nv_bfloat16 g_Amm_hi [M_ROWS * DIM];
__device__ __align__(16) __nv_bfloat16 g_Amm_lo [M_ROWS * DIM];
__device__ __align__(16) __nv_bfloat16 g_Asrc_hi[M_ROWS * DIM];
__device__ __align__(16) __nv_bfloat16 g_Asrc_lo[M_ROWS * DIM];
__device__ __align__(16) __nv_bfloat16 g_AO_hi  [M_ROWS * DIM];
__device__ __align__(16) __nv_bfloat16 g_AO_lo  [M_ROWS * DIM];
__device__ __align__(16) __nv_bfloat16 g_WqT_hi [DIM * DIM];      // [n][k]
__device__ __align__(16) __nv_bfloat16 g_WqT_lo [DIM * DIM];
__device__ __align__(16) __nv_bfloat16 g_WkvT_hi[2 * DIM * DIM];
__device__ __align__(16) __nv_bfloat16 g_WkvT_lo[2 * DIM * DIM];
__device__ __align__(16) __nv_bfloat16 g_WpT_hi [DIM * DIM];
__device__ __align__(16) __nv_bfloat16 g_WpT_lo [DIM * DIM];

// ---------------- PTX helpers (all plain-sm_103-legal) ---------------------
__device__ __forceinline__ uint32_t smem_u32(const void* p) {
    uint32_t a;
    asm("{ .reg .u64 t; cvta.to.shared.u64 t, %1; cvt.u32.u64 %0, t; }" : "=r"(a) : "l"(p));
    return a;
}
__device__ __forceinline__ void cp_async16(uint32_t dst, const void* src) {
    asm volatile("cp.async.cg.shared.global [%0], [%1], 16;" :: "r"(dst), "l"(src));
}
__device__ __forceinline__ void cp_commit() {
    asm volatile("cp.async.commit_group;" ::: "memory");
}
template <int N>
__device__ __forceinline__ void cp_wait() {
    asm volatile("cp.async.wait_group %0;" :: "n"(N) : "memory");
}
__device__ __forceinline__ void ldmatrix_x4(uint32_t& r0, uint32_t& r1, uint32_t& r2,
                                            uint32_t& r3, uint32_t addr) {
    asm volatile("ldmatrix.sync.aligned.m8n8.x4.shared.b16 {%0,%1,%2,%3}, [%4];"
                 : "=r"(r0), "=r"(r1), "=r"(r2), "=r"(r3) : "r"(addr));
}
__device__ __forceinline__ void mma_bf16(float* c, const uint32_t* a, const uint32_t* b) {
    asm volatile(
        "mma.sync.aligned.m16n8k16.row.col.f32.bf16.bf16.f32 "
        "{%0,%1,%2,%3}, {%4,%5,%6,%7}, {%8,%9}, {%0,%1,%2,%3};"
        : "+f"(c[0]), "+f"(c[1]), "+f"(c[2]), "+f"(c[3])
        : "r"(a[0]), "r"(a[1]), "r"(a[2]), "r"(a[3]), "r"(b[0]), "r"(b[1]));
}

// ---------------- prep kernels ---------------------------------------------
template <int DST>   // 0: xmm -> g_Amm,  1: g_O -> g_AO
__global__ void k_split(const float* __restrict__ s) {
    const int i = blockIdx.x * 256 + threadIdx.x;
    if (i >= M_ROWS * DIM / 2) return;
    const float2 v = (DST == 0) ? reinterpret_cast<const float2*>(s)[i]
                                : reinterpret_cast<const float2*>(g_O)[i];
    __nv_bfloat16 h0 = __float2bfloat16(v.x), h1 = __float2bfloat16(v.y);
    __nv_bfloat162 hh = __halves2bfloat162(h0, h1);
    __nv_bfloat162 ll = __halves2bfloat162(
        __float2bfloat16(v.x - __bfloat162float(h0)),
        __float2bfloat16(v.y - __bfloat162float(h1)));
    if (DST == 0) {
        reinterpret_cast<__nv_bfloat162*>(g_Amm_hi)[i] = hh;
        reinterpret_cast<__nv_bfloat162*>(g_Amm_lo)[i] = ll;
    } else {
        reinterpret_cast<__nv_bfloat162*>(g_AO_hi)[i] = hh;
        reinterpret_cast<__nv_bfloat162*>(g_AO_lo)[i] = ll;
    }
}

__global__ void k_split_gather(const float* __restrict__ xv, const float* __restrict__ xa) {
    const int u = blockIdx.x * 256 + threadIdx.x;
    if (u >= M_ROWS * DIM / 2) return;
    const int row = u / (DIM / 2), c2 = u - row * (DIM / 2);
    const int b = row >> 8, t = row & 255;
    const float* src = (t < NV) ? xv + ((size_t)(b * NV + t)) * DIM
                                : xa + ((size_t)(b * NA + (t - NV))) * DIM;
    const float2 v = reinterpret_cast<const float2*>(src)[c2];
    __nv_bfloat16 h0 = __float2bfloat16(v.x), h1 = __float2bfloat16(v.y);
    reinterpret_cast<__nv_bfloat162*>(g_Asrc_hi)[u] = __halves2bfloat162(h0, h1);
    reinterpret_cast<__nv_bfloat162*>(g_Asrc_lo)[u] = __halves2bfloat162(
        __float2bfloat16(v.x - __bfloat162float(h0)),
        __float2bfloat16(v.y - __bfloat162float(h1)));
}

template <int WSEL>   // 0=Wq, 1=Wkv, 2=Wproj  : W [768][N] -> WT hi/lo [N][768]
__global__ void k_transpose_split(const float* __restrict__ W, int N) {
    __shared__ float t[32][33];
    const int n0 = blockIdx.x * 32, k0 = blockIdx.y * 32;
    const int tx = threadIdx.x & 31, ty = threadIdx.x >> 5;   // 32 x 8
#pragma unroll
    for (int i = 0; i < 4; i++)
        t[ty + 8 * i][tx] = W[(size_t)(k0 + ty + 8 * i) * N + n0 + tx];
    __syncthreads();
    __nv_bfloat16* Thi = (WSEL == 0) ? g_WqT_hi : (WSEL == 1) ? g_WkvT_hi : g_WpT_hi;
    __nv_bfloat16* Tlo = (WSEL == 0) ? g_WqT_lo : (WSEL == 1) ? g_WkvT_lo : g_WpT_lo;
#pragma unroll
    for (int i = 0; i < 4; i++) {
        const float x = t[tx][ty + 8 * i];
        const __nv_bfloat16 h = __float2bfloat16(x);
        const size_t o = (size_t)(n0 + ty + 8 * i) * DIM + k0 + tx;
        Thi[o] = h;
        Tlo[o] = __float2bfloat16(x - __bfloat162float(h));
    }
}

// ---------------- mma.sync GEMM --------------------------------------------
// C[M,N] = A[M,768] @ B^T  (B stored [N][768] K-major), bf16 hi/lo split,
// fp32 acc: C = Ah*Bh + Ah*Bl + Al*Bh.  CTA 128x128, 8 warps (64x32 each),
// BK=32, cp.async double buffer, xor-swizzled 64B smem rows.
// MODE 0: Q-proj -> g_Q [b,h,q,d]; 1: KV-proj -> g_K/g_V; 2: O-proj -> C+bias
#define TILE_B   8192               // one 128x32 bf16 tile, bytes
#define BUF_B    (4 * TILE_B)       // Ah, Al, Bh, Bl
__device__ __forceinline__ uint32_t sw_off(int row, int c16) {
    return (uint32_t)(row * 64 + ((c16 ^ ((row >> 1) & 3)) << 4));
}

template <int MODE>
__global__ __launch_bounds__(256, 1)
void tc_gemm(const float* __restrict__ bias, float* __restrict__ C)
{
    extern __shared__ char smem[];
    const uint32_t sb = smem_u32(smem);
    const int tid = threadIdx.x, wid = tid >> 5, lane = tid & 31;
    const int m0 = blockIdx.y * 128, n0 = blockIdx.x * 128;
    const int wm = wid & 1, wn = wid >> 1;          // warp tile (wm*64, wn*32)

    const __nv_bfloat16* Ahi = (MODE == 0) ? g_Amm_hi : (MODE == 1) ? g_Asrc_hi : g_AO_hi;
    const __nv_bfloat16* Alo = (MODE == 0) ? g_Amm_lo : (MODE == 1) ? g_Asrc_lo : g_AO_lo;
    const __nv_bfloat16* Bhi = (MODE == 0) ? g_WqT_hi : (MODE == 1) ? g_WkvT_hi : g_WpT_hi;
    const __nv_bfloat16* Blo = (MODE == 0) ? g_WqT_lo : (MODE == 1) ? g_WkvT_lo : g_WpT_lo;

    const char* gsrc[4] = {
        (const char*)(Ahi + (size_t)m0 * DIM), (const char*)(Alo + (size_t)m0 * DIM),
        (const char*)(Bhi + (size_t)n0 * DIM), (const char*)(Blo + (size_t)n0 * DIM) };

    // per-thread cp.async mapping: 2 chunks per tile (512 chunks / 256 thr)
    const int ck0 = tid, ck1 = tid + 256;

    auto issue = [&](int it) {
        const int kb = it * 64;                      // byte offset of k0 in a row
        const uint32_t bufb = sb + (uint32_t)(it & 1) * BUF_B;
#pragma unroll
        for (int t = 0; t < 4; t++) {
            {
                const int row = ck0 >> 2, c16 = ck0 & 3;
                cp_async16(bufb + t * TILE_B + sw_off(row, c16),
                           gsrc[t] + (size_t)row * (DIM * 2) + kb + c16 * 16);
            }
            {
                const int row = ck1 >> 2, c16 = ck1 & 3;
                cp_async16(bufb + t * TILE_B + sw_off(row, c16),
                           gsrc[t] + (size_t)row * (DIM * 2) + kb + c16 * 16);
            }
        }
        cp_commit();
    };

    float acc[4][4][4];
#pragma unroll
    for (int i = 0; i < 4; i++)
#pragma unroll
        for (int j = 0; j < 4; j++)
#pragma unroll
            for (int r = 0; r < 4; r++) acc[i][j][r] = 0.f;

    // ldmatrix lane address components
    const int matA = lane >> 3, wiA = lane & 7;
    const int a_moff = ((matA & 1) << 3) + wiA;       // row within m16
    const int a_ksel = matA >> 1;                      // 0/1 -> k16 half
    const int b_noff = ((matA >> 1) << 3) + wiA;       // row within n16
    const int b_ksel = matA & 1;

    issue(0);

    const int NITER = DIM / 32;                        // 24
    for (int it = 0; it < NITER; it++) {
        if (it + 1 < NITER) { issue(it + 1); cp_wait<1>(); }
        else                 cp_wait<0>();
        __syncthreads();

        const uint32_t bufb = sb + (uint32_t)(it & 1) * BUF_B;
        const uint32_t sAh = bufb, sAl = bufb + TILE_B;
        const uint32_t sBh = bufb + 2 * TILE_B, sBl = bufb + 3 * TILE_B;

#pragma unroll
        for (int kk = 0; kk < 2; kk++) {               // two k16 halves
            uint32_t ah[4][4], al[4][4], bh[2][4], bl[2][4];
#pragma unroll
            for (int mi = 0; mi < 4; mi++) {
                const int row = wm * 64 + mi * 16 + a_moff;
                const uint32_t o = sw_off(row, kk * 2 + a_ksel);
                ldmatrix_x4(ah[mi][0], ah[mi][1], ah[mi][2], ah[mi][3], sAh + o);
                ldmatrix_x4(al[mi][0], al[mi][1], al[mi][2], al[mi][3], sAl + o);
            }
#pragma unroll
            for (int ni = 0; ni < 2; ni++) {
                const int row = wn * 32 + ni * 16 + b_noff;
                const uint32_t o = sw_off(row, kk * 2 + b_ksel);
                ldmatrix_x4(bh[ni][0], bh[ni][1], bh[ni][2], bh[ni][3], sBh + o);
                ldmatrix_x4(bl[ni][0], bl[ni][1], bl[ni][2], bl[ni][3], sBl + o);
            }
#pragma unroll
            for (int mi = 0; mi < 4; mi++)
#pragma unroll
                for (int n8 = 0; n8 < 4; n8++) {
                    const int ni = n8 >> 1, p = (n8 & 1) << 1;
                    uint32_t bfh[2] = { bh[ni][p], bh[ni][p + 1] };
                    uint32_t bfl[2] = { bl[ni][p], bl[ni][p + 1] };
                    mma_bf16(acc[mi][n8], ah[mi], bfh);   // hi*hi
                    mma_bf16(acc[mi][n8], ah[mi], bfl);   // hi*lo
                    mma_bf16(acc[mi][n8], al[mi], bfh);   // lo*hi
                }
        }
        __syncthreads();
    }

    // ---- epilogue ----
    const int gi = lane >> 2, qi = lane & 3;
#pragma unroll
    for (int mi = 0; mi < 4; mi++)
#pragma unroll
        for (int n8 = 0; n8 < 4; n8++)
#pragma unroll
            for (int half = 0; half < 2; half++) {
                const int r  = m0 + wm * 64 + mi * 16 + gi + half * 8;
                const int cg = n0 + wn * 32 + n8 * 8 + qi * 2;
                float2 v = make_float2(acc[mi][n8][2 * half], acc[mi][n8][2 * half + 1]);
                if (MODE == 0) {
                    const int b = r >> 8, q = r & 255, h = cg >> 6, d = cg & 63;
                    *reinterpret_cast<float2*>(&g_Q[(((size_t)b * HEADS + h) * NMM + q) * HD + d]) = v;
                } else if (MODE == 1) {
                    const int b = r >> 8, t = r & 255;
                    if (cg < DIM) {
                        const int h = cg >> 6, d = cg & 63;
                        *reinterpret_cast<float2*>(&g_K[(((size_t)b * HEADS + h) * NKV + t) * HD + d]) = v;
                    } else {
                        const int c2 = cg - DIM, h = c2 >> 6, d = c2 & 63;
                        *reinterpret_cast<float2*>(&g_V[(((size_t)b * HEADS + h) * NKV + t) * HD + d]) = v;
                    }
                } else {
                    v.x += bias[cg]; v.y += bias[cg + 1];
                    *reinterpret_cast<float2*>(&C[(size_t)r * DIM + cg]) = v;
                }
            }
}

// ---------------- attention (fp32, unchanged) ------------------------------
__global__ __launch_bounds__(256, 1)
void attn_kernel(float* __restrict__ attn)
{
    extern __shared__ float sh[];
    float* Ksh = sh;
    float* Vsh = sh + NKV * HD;

    const int bh = blockIdx.x;
    const int b = bh / HEADS, h = bh - b * HEADS;
    const int tid = threadIdx.x;

    const float4* kg = reinterpret_cast<const float4*>(g_K + (size_t)bh * NKV * HD);
    const float4* vg = reinterpret_cast<const float4*>(g_V + (size_t)bh * NKV * HD);
    float4* k4 = reinterpret_cast<float4*>(Ksh);
    float4* v4 = reinterpret_cast<float4*>(Vsh);
#pragma unroll 4
    for (int i = tid; i < NKV * HD / 4; i += 256) { k4[i] = kg[i]; v4[i] = vg[i]; }
    __syncthreads();

    const int q = tid;
    float qreg[HD];
    const float4* qg = reinterpret_cast<const float4*>(g_Q + ((size_t)bh * NMM + q) * HD);
#pragma unroll
    for (int i = 0; i < HD / 4; i++)
        *reinterpret_cast<float4*>(&qreg[4 * i]) = qg[i];

    const float scale = 0.125f;

    float m = -INFINITY, l = 0.f;
    for (int k = 0; k < NKV; k++) {
        const float* kr = Ksh + k * HD;
        float s = 0.f;
#pragma unroll
        for (int d = 0; d < HD; d++) s += qreg[d] * kr[d];
        s *= scale;
        const float mn = fmaxf(m, s);
        l = l * __expf(m - mn) + __expf(s - mn);
        m = mn;
    }
    const float inv = 1.0f / l;

    float o[HD];
#pragma unroll
    for (int d = 0; d < HD; d++) o[d] = 0.f;

    float* arow = attn + ((size_t)bh * NMM + q) * NKV;
    for (int k = 0; k < NKV; k += 4) {
        float ps[4];
#pragma unroll
        for (int u = 0; u < 4; u++) {
            const float* kr = Ksh + (k + u) * HD;
            float s = 0.f;
#pragma unroll
            for (int d = 0; d < HD; d++) s += qreg[d] * kr[d];
            const float p = __expf(s * scale - m) * inv;
            ps[u] = p;
            const float* vr = Vsh + (k + u) * HD;
#pragma unroll
            for (int d = 0; d < HD; d++) o[d] += p * vr[d];
        }
        *reinterpret_cast<float4*>(arow + k) = make_float4(ps[0], ps[1], ps[2], ps[3]);
    }

    float* op = g_O + ((size_t)b * NMM + q) * DIM + h * HD;
#pragma unroll
    for (int i = 0; i < HD / 4; i++)
        reinterpret_cast<float4*>(op)[i] = *reinterpret_cast<const float4*>(&o[4 * i]);
}

// ---------------------------------------------------------------------------
extern "C" void kernel_launch(void* const* d_in, const int* in_sizes, int n_in,
                              void* d_out, int out_size)
{
    const float* xmm   = (const float*)d_in[0];
    const float* xv    = (const float*)d_in[1];
    const float* xa    = (const float*)d_in[2];
    const float* Wq    = (const float*)d_in[3];
    const float* Wkv   = (const float*)d_in[4];
    const float* Wproj = (const float*)d_in[5];
    const float* bproj = (const float*)d_in[6];

    float* out  = (float*)d_out;
    float* attn = out + (size_t)BS * NMM * DIM;

    const int GEMM_SMEM = 2 * BUF_B;                         // 64 KB
    const int ATTN_SMEM = 2 * NKV * HD * (int)sizeof(float); // 128 KB
    cudaFuncSetAttribute(tc_gemm<0>, cudaFuncAttributeMaxDynamicSharedMemorySize, GEMM_SMEM);
    cudaFuncSetAttribute(tc_gemm<1>, cudaFuncAttributeMaxDynamicSharedMemorySize, GEMM_SMEM);
    cudaFuncSetAttribute(tc_gemm<2>, cudaFuncAttributeMaxDynamicSharedMemorySize, GEMM_SMEM);
    cudaFuncSetAttribute(attn_kernel, cudaFuncAttributeMaxDynamicSharedMemorySize, ATTN_SMEM);

    const int nsplit = M_ROWS * DIM / 2;
    k_split<0><<<(nsplit + 255) / 256, 256>>>(xmm);
    k_split_gather<<<(nsplit + 255) / 256, 256>>>(xv, xa);
    k_transpose_split<0><<<dim3(DIM / 32, DIM / 32), 256>>>(Wq, DIM);
    k_transpose_split<1><<<dim3(2 * DIM / 32, DIM / 32), 256>>>(Wkv, 2 * DIM);
    k_transpose_split<2><<<dim3(DIM / 32, DIM / 32), 256>>>(Wproj, DIM);

    tc_gemm<0><<<dim3(DIM / 128, M_ROWS / 128), 256, GEMM_SMEM>>>(nullptr, nullptr);
    tc_gemm<1><<<dim3(2 * DIM / 128, M_ROWS / 128), 256, GEMM_SMEM>>>(nullptr, nullptr);

    attn_kernel<<<BS * HEADS, 256, ATTN_SMEM>>>(attn);

    k_split<1><<<(nsplit + 255) / 256, 256>>>(nullptr);
    tc_gemm<2><<<dim3(DIM / 128, M_ROWS / 128), 256, GEMM_SMEM>>>(bproj, out);
}

// round 7
// speedup vs baseline: 2.6169x; 1.5149x over previous
#include <cuda_runtime.h>
#include <cuda_bf16.h>
#include <math.h>
#include <stdint.h>

#define DIM   768
#define HEADS 12
#define HD    64
#define BS    32
#define NMM   256
#define NV    196
#define NA    60
#define NKV   256
#define M_ROWS (BS * NMM)       // 8192

// ---------------- scratch (device globals; no cudaMalloc allowed) ----------
__device__ __align__(16) __nv_bfloat16 g_Qh[BS * HEADS * NMM * HD];  // [b,h,q,d] (pre-scaled)
__device__ __align__(16) __nv_bfloat16 g_Ql[BS * HEADS * NMM * HD];
__device__ __align__(16) __nv_bfloat16 g_Kh[BS * HEADS * NKV * HD];  // [b,h,k,d]
__device__ __align__(16) __nv_bfloat16 g_Kl[BS * HEADS * NKV * HD];
__device__ __align__(16) __nv_bfloat16 g_VTh[BS * HEADS * HD * NKV]; // [b,h,d,k]
__device__ __align__(16) __nv_bfloat16 g_VTl[BS * HEADS * HD * NKV];
__device__ __align__(16) __nv_bfloat16 g_Ph[BS * HEADS * NMM * NKV]; // [bh,q,k]
__device__ __align__(16) __nv_bfloat16 g_Pl[BS * HEADS * NMM * NKV];

__device__ __align__(16) __nv_bfloat16 g_Amm_hi [M_ROWS * DIM];
__device__ __align__(16) __nv_bfloat16 g_Amm_lo [M_ROWS * DIM];
__device__ __align__(16) __nv_bfloat16 g_Asrc_hi[M_ROWS * DIM];
__device__ __align__(16) __nv_bfloat16 g_Asrc_lo[M_ROWS * DIM];
__device__ __align__(16) __nv_bfloat16 g_AO_hi  [M_ROWS * DIM];
__device__ __align__(16) __nv_bfloat16 g_AO_lo  [M_ROWS * DIM];
__device__ __align__(16) __nv_bfloat16 g_WqT_hi [DIM * DIM];      // [n][k]
__device__ __align__(16) __nv_bfloat16 g_WqT_lo [DIM * DIM];
__device__ __align__(16) __nv_bfloat16 g_WkvT_hi[2 * DIM * DIM];
__device__ __align__(16) __nv_bfloat16 g_WkvT_lo[2 * DIM * DIM];
__device__ __align__(16) __nv_bfloat16 g_WpT_hi [DIM * DIM];
__device__ __align__(16) __nv_bfloat16 g_WpT_lo [DIM * DIM];

// ---------------- PTX helpers (plain-sm_103-legal) -------------------------
__device__ __forceinline__ uint32_t smem_u32(const void* p) {
    uint32_t a;
    asm("{ .reg .u64 t; cvta.to.shared.u64 t, %1; cvt.u32.u64 %0, t; }" : "=r"(a) : "l"(p));
    return a;
}
__device__ __forceinline__ void cp_async16(uint32_t dst, const void* src) {
    asm volatile("cp.async.cg.shared.global [%0], [%1], 16;" :: "r"(dst), "l"(src));
}
__device__ __forceinline__ void cp_commit() {
    asm volatile("cp.async.commit_group;" ::: "memory");
}
template <int N>
__device__ __forceinline__ void cp_wait() {
    asm volatile("cp.async.wait_group %0;" :: "n"(N) : "memory");
}
__device__ __forceinline__ void ldmatrix_x4(uint32_t& r0, uint32_t& r1, uint32_t& r2,
                                            uint32_t& r3, uint32_t addr) {
    asm volatile("ldmatrix.sync.aligned.m8n8.x4.shared.b16 {%0,%1,%2,%3}, [%4];"
                 : "=r"(r0), "=r"(r1), "=r"(r2), "=r"(r3) : "r"(addr));
}
__device__ __forceinline__ void mma_bf16(float* c, const uint32_t* a, const uint32_t* b) {
    asm volatile(
        "mma.sync.aligned.m16n8k16.row.col.f32.bf16.bf16.f32 "
        "{%0,%1,%2,%3}, {%4,%5,%6,%7}, {%8,%9}, {%0,%1,%2,%3};"
        : "+f"(c[0]), "+f"(c[1]), "+f"(c[2]), "+f"(c[3])
        : "r"(a[0]), "r"(a[1]), "r"(a[2]), "r"(a[3]), "r"(b[0]), "r"(b[1]));
}
__device__ __forceinline__ void bfsplit(float x, __nv_bfloat16& hi, __nv_bfloat16& lo) {
    hi = __float2bfloat16(x);
    lo = __float2bfloat16(x - __bfloat162float(hi));
}

// ---------------- prep kernels ---------------------------------------------
__global__ void k_split(const float* __restrict__ s) {      // xmm -> g_Amm
    const int i = blockIdx.x * 256 + threadIdx.x;
    if (i >= M_ROWS * DIM / 2) return;
    const float2 v = reinterpret_cast<const float2*>(s)[i];
    __nv_bfloat16 h0, l0, h1, l1;
    bfsplit(v.x, h0, l0); bfsplit(v.y, h1, l1);
    reinterpret_cast<__nv_bfloat162*>(g_Amm_hi)[i] = __halves2bfloat162(h0, h1);
    reinterpret_cast<__nv_bfloat162*>(g_Amm_lo)[i] = __halves2bfloat162(l0, l1);
}

__global__ void k_split_gather(const float* __restrict__ xv, const float* __restrict__ xa) {
    const int u = blockIdx.x * 256 + threadIdx.x;
    if (u >= M_ROWS * DIM / 2) return;
    const int row = u / (DIM / 2), c2 = u - row * (DIM / 2);
    const int b = row >> 8, t = row & 255;
    const float* src = (t < NV) ? xv + ((size_t)(b * NV + t)) * DIM
                                : xa + ((size_t)(b * NA + (t - NV))) * DIM;
    const float2 v = reinterpret_cast<const float2*>(src)[c2];
    __nv_bfloat16 h0, l0, h1, l1;
    bfsplit(v.x, h0, l0); bfsplit(v.y, h1, l1);
    reinterpret_cast<__nv_bfloat162*>(g_Asrc_hi)[u] = __halves2bfloat162(h0, h1);
    reinterpret_cast<__nv_bfloat162*>(g_Asrc_lo)[u] = __halves2bfloat162(l0, l1);
}

template <int WSEL>   // 0=Wq, 1=Wkv, 2=Wproj  : W [768][N] -> WT hi/lo [N][768]
__global__ void k_transpose_split(const float* __restrict__ W, int N) {
    __shared__ float t[32][33];
    const int n0 = blockIdx.x * 32, k0 = blockIdx.y * 32;
    const int tx = threadIdx.x & 31, ty = threadIdx.x >> 5;   // 32 x 8
#pragma unroll
    for (int i = 0; i < 4; i++)
        t[ty + 8 * i][tx] = W[(size_t)(k0 + ty + 8 * i) * N + n0 + tx];
    __syncthreads();
    __nv_bfloat16* Thi = (WSEL == 0) ? g_WqT_hi : (WSEL == 1) ? g_WkvT_hi : g_WpT_hi;
    __nv_bfloat16* Tlo = (WSEL == 0) ? g_WqT_lo : (WSEL == 1) ? g_WkvT_lo : g_WpT_lo;
#pragma unroll
    for (int i = 0; i < 4; i++) {
        const float x = t[tx][ty + 8 * i];
        __nv_bfloat16 h, l;
        bfsplit(x, h, l);
        const size_t o = (size_t)(n0 + ty + 8 * i) * DIM + k0 + tx;
        Thi[o] = h; Tlo[o] = l;
    }
}

// ---------------- projection GEMMs (mma.sync, bf16 hi/lo) ------------------
#define TILE_B   8192               // one 128x32 bf16 tile, bytes
#define BUF_B    (4 * TILE_B)
__device__ __forceinline__ uint32_t sw_off(int row, int c16) {
    return (uint32_t)(row * 64 + ((c16 ^ ((row >> 1) & 3)) << 4));
}

template <int MODE>   // 0: Q-proj, 1: KV-proj, 2: O-proj
__global__ __launch_bounds__(256, 1)
void tc_gemm(const float* __restrict__ bias, float* __restrict__ C)
{
    extern __shared__ char smem[];
    const uint32_t sb = smem_u32(smem);
    const int tid = threadIdx.x, wid = tid >> 5, lane = tid & 31;
    const int m0 = blockIdx.y * 128, n0 = blockIdx.x * 128;
    const int wm = wid & 1, wn = wid >> 1;

    const __nv_bfloat16* Ahi = (MODE == 0) ? g_Amm_hi : (MODE == 1) ? g_Asrc_hi : g_AO_hi;
    const __nv_bfloat16* Alo = (MODE == 0) ? g_Amm_lo : (MODE == 1) ? g_Asrc_lo : g_AO_lo;
    const __nv_bfloat16* Bhi = (MODE == 0) ? g_WqT_hi : (MODE == 1) ? g_WkvT_hi : g_WpT_hi;
    const __nv_bfloat16* Blo = (MODE == 0) ? g_WqT_lo : (MODE == 1) ? g_WkvT_lo : g_WpT_lo;

    const char* gsrc[4] = {
        (const char*)(Ahi + (size_t)m0 * DIM), (const char*)(Alo + (size_t)m0 * DIM),
        (const char*)(Bhi + (size_t)n0 * DIM), (const char*)(Blo + (size_t)n0 * DIM) };

    const int ck0 = tid, ck1 = tid + 256;
    auto issue = [&](int it) {
        const int kb = it * 64;
        const uint32_t bufb = sb + (uint32_t)(it & 1) * BUF_B;
#pragma unroll
        for (int t = 0; t < 4; t++) {
            { const int row = ck0 >> 2, c16 = ck0 & 3;
              cp_async16(bufb + t * TILE_B + sw_off(row, c16),
                         gsrc[t] + (size_t)row * (DIM * 2) + kb + c16 * 16); }
            { const int row = ck1 >> 2, c16 = ck1 & 3;
              cp_async16(bufb + t * TILE_B + sw_off(row, c16),
                         gsrc[t] + (size_t)row * (DIM * 2) + kb + c16 * 16); }
        }
        cp_commit();
    };

    float acc[4][4][4];
#pragma unroll
    for (int i = 0; i < 4; i++)
#pragma unroll
        for (int j = 0; j < 4; j++)
#pragma unroll
            for (int r = 0; r < 4; r++) acc[i][j][r] = 0.f;

    const int matA = lane >> 3, wiA = lane & 7;
    const int a_moff = ((matA & 1) << 3) + wiA;
    const int a_ksel = matA >> 1;
    const int b_noff = ((matA >> 1) << 3) + wiA;
    const int b_ksel = matA & 1;

    issue(0);
    const int NITER = DIM / 32;                        // 24
    for (int it = 0; it < NITER; it++) {
        if (it + 1 < NITER) { issue(it + 1); cp_wait<1>(); }
        else                 cp_wait<0>();
        __syncthreads();
        const uint32_t bufb = sb + (uint32_t)(it & 1) * BUF_B;
        const uint32_t sAh = bufb, sAl = bufb + TILE_B;
        const uint32_t sBh = bufb + 2 * TILE_B, sBl = bufb + 3 * TILE_B;
#pragma unroll
        for (int kk = 0; kk < 2; kk++) {
            uint32_t ah[4][4], al[4][4], bh[2][4], bl[2][4];
#pragma unroll
            for (int mi = 0; mi < 4; mi++) {
                const int row = wm * 64 + mi * 16 + a_moff;
                const uint32_t o = sw_off(row, kk * 2 + a_ksel);
                ldmatrix_x4(ah[mi][0], ah[mi][1], ah[mi][2], ah[mi][3], sAh + o);
                ldmatrix_x4(al[mi][0], al[mi][1], al[mi][2], al[mi][3], sAl + o);
            }
#pragma unroll
            for (int ni = 0; ni < 2; ni++) {
                const int row = wn * 32 + ni * 16 + b_noff;
                const uint32_t o = sw_off(row, kk * 2 + b_ksel);
                ldmatrix_x4(bh[ni][0], bh[ni][1], bh[ni][2], bh[ni][3], sBh + o);
                ldmatrix_x4(bl[ni][0], bl[ni][1], bl[ni][2], bl[ni][3], sBl + o);
            }
#pragma unroll
            for (int mi = 0; mi < 4; mi++)
#pragma unroll
                for (int n8 = 0; n8 < 4; n8++) {
                    const int ni = n8 >> 1, p = (n8 & 1) << 1;
                    uint32_t bfh[2] = { bh[ni][p], bh[ni][p + 1] };
                    uint32_t bfl[2] = { bl[ni][p], bl[ni][p + 1] };
                    mma_bf16(acc[mi][n8], ah[mi], bfh);
                    mma_bf16(acc[mi][n8], ah[mi], bfl);
                    mma_bf16(acc[mi][n8], al[mi], bfh);
                }
        }
        __syncthreads();
    }

    const int gi = lane >> 2, qi = lane & 3;
#pragma unroll
    for (int mi = 0; mi < 4; mi++)
#pragma unroll
        for (int n8 = 0; n8 < 4; n8++)
#pragma unroll
            for (int half = 0; half < 2; half++) {
                const int r  = m0 + wm * 64 + mi * 16 + gi + half * 8;
                const int cg = n0 + wn * 32 + n8 * 8 + qi * 2;
                float2 v = make_float2(acc[mi][n8][2 * half], acc[mi][n8][2 * half + 1]);
                if (MODE == 0) {
                    v.x *= 0.125f; v.y *= 0.125f;          // fold 1/sqrt(hd), exact
                    const int b = r >> 8, q = r & 255, h = cg >> 6, d = cg & 63;
                    __nv_bfloat16 hx, lx, hy, ly;
                    bfsplit(v.x, hx, lx); bfsplit(v.y, hy, ly);
                    const size_t o = (((size_t)b * HEADS + h) * NMM + q) * HD + d;
                    *reinterpret_cast<__nv_bfloat162*>(&g_Qh[o]) = __halves2bfloat162(hx, hy);
                    *reinterpret_cast<__nv_bfloat162*>(&g_Ql[o]) = __halves2bfloat162(lx, ly);
                } else if (MODE == 1) {
                    const int b = r >> 8, t = r & 255;
                    __nv_bfloat16 hx, lx, hy, ly;
                    bfsplit(v.x, hx, lx); bfsplit(v.y, hy, ly);
                    if (cg < DIM) {
                        const int h = cg >> 6, d = cg & 63;
                        const size_t o = (((size_t)b * HEADS + h) * NKV + t) * HD + d;
                        *reinterpret_cast<__nv_bfloat162*>(&g_Kh[o]) = __halves2bfloat162(hx, hy);
                        *reinterpret_cast<__nv_bfloat162*>(&g_Kl[o]) = __halves2bfloat162(lx, ly);
                    } else {
                        const int c2 = cg - DIM, h = c2 >> 6, d = c2 & 63;
                        const size_t vb = ((size_t)b * HEADS + h) * HD;
                        g_VTh[(vb + d) * NKV + t] = hx; g_VTh[(vb + d + 1) * NKV + t] = hy;
                        g_VTl[(vb + d) * NKV + t] = lx; g_VTl[(vb + d + 1) * NKV + t] = ly;
                    }
                } else {
                    v.x += bias[cg]; v.y += bias[cg + 1];
                    *reinterpret_cast<float2*>(&C[(size_t)r * DIM + cg]) = v;
                }
            }
}

// ---------------- S = (Q*scale) @ K^T (batched, hi/lo) ---------------------
__global__ __launch_bounds__(256, 1)
void s_gemm(float* __restrict__ attn)
{
    extern __shared__ char smem[];
    const uint32_t sb = smem_u32(smem);
    const int tid = threadIdx.x, wid = tid >> 5, lane = tid & 31;
    const int m0 = blockIdx.y * 128, n0 = blockIdx.x * 128, bh = blockIdx.z;
    const int wm = wid & 1, wn = wid >> 1;

    const char* gsrc[4] = {
        (const char*)(g_Qh + ((size_t)bh * NMM + m0) * HD),
        (const char*)(g_Ql + ((size_t)bh * NMM + m0) * HD),
        (const char*)(g_Kh + ((size_t)bh * NKV + n0) * HD),
        (const char*)(g_Kl + ((size_t)bh * NKV + n0) * HD) };

    const int ck0 = tid, ck1 = tid + 256;
    auto issue = [&](int it) {
        const int kb = it * 64;
        const uint32_t bufb = sb + (uint32_t)(it & 1) * BUF_B;
#pragma unroll
        for (int t = 0; t < 4; t++) {
            { const int row = ck0 >> 2, c16 = ck0 & 3;
              cp_async16(bufb + t * TILE_B + sw_off(row, c16),
                         gsrc[t] + (size_t)row * 128 + kb + c16 * 16); }
            { const int row = ck1 >> 2, c16 = ck1 & 3;
              cp_async16(bufb + t * TILE_B + sw_off(row, c16),
                         gsrc[t] + (size_t)row * 128 + kb + c16 * 16); }
        }
        cp_commit();
    };

    float acc[4][4][4];
#pragma unroll
    for (int i = 0; i < 4; i++)
#pragma unroll
        for (int j = 0; j < 4; j++)
#pragma unroll
            for (int r = 0; r < 4; r++) acc[i][j][r] = 0.f;

    const int matA = lane >> 3, wiA = lane & 7;
    const int a_moff = ((matA & 1) << 3) + wiA;
    const int a_ksel = matA >> 1;
    const int b_noff = ((matA >> 1) << 3) + wiA;
    const int b_ksel = matA & 1;

    issue(0);
    for (int it = 0; it < 2; it++) {                   // K=64 -> 2 x BK32
        if (it == 0) { issue(1); cp_wait<1>(); }
        else         cp_wait<0>();
        __syncthreads();
        const uint32_t bufb = sb + (uint32_t)(it & 1) * BUF_B;
        const uint32_t sAh = bufb, sAl = bufb + TILE_B;
        const uint32_t sBh = bufb + 2 * TILE_B, sBl = bufb + 3 * TILE_B;
#pragma unroll
        for (int kk = 0; kk < 2; kk++) {
            uint32_t ah[4][4], al[4][4], bh[2][4], bl[2][4];
#pragma unroll
            for (int mi = 0; mi < 4; mi++) {
                const int row = wm * 64 + mi * 16 + a_moff;
                const uint32_t o = sw_off(row, kk * 2 + a_ksel);
                ldmatrix_x4(ah[mi][0], ah[mi][1], ah[mi][2], ah[mi][3], sAh + o);
                ldmatrix_x4(al[mi][0], al[mi][1], al[mi][2], al[mi][3], sAl + o);
            }
#pragma unroll
            for (int ni = 0; ni < 2; ni++) {
                const int row = wn * 32 + ni * 16 + b_noff;
                const uint32_t o = sw_off(row, kk * 2 + b_ksel);
                ldmatrix_x4(bh[ni][0], bh[ni][1], bh[ni][2], bh[ni][3], sBh + o);
                ldmatrix_x4(bl[ni][0], bl[ni][1], bl[ni][2], bl[ni][3], sBl + o);
            }
#pragma unroll
            for (int mi = 0; mi < 4; mi++)
#pragma unroll
                for (int n8 = 0; n8 < 4; n8++) {
                    const int ni = n8 >> 1, p = (n8 & 1) << 1;
                    uint32_t bfh[2] = { bh[ni][p], bh[ni][p + 1] };
                    uint32_t bfl[2] = { bl[ni][p], bl[ni][p + 1] };
                    mma_bf16(acc[mi][n8], ah[mi], bfh);
                    mma_bf16(acc[mi][n8], ah[mi], bfl);
                    mma_bf16(acc[mi][n8], al[mi], bfh);
                }
        }
        __syncthreads();
    }

    const int gi = lane >> 2, qi = lane & 3;
    float* outp = attn + (size_t)bh * NMM * NKV;
#pragma unroll
    for (int mi = 0; mi < 4; mi++)
#pragma unroll
        for (int n8 = 0; n8 < 4; n8++)
#pragma unroll
            for (int half = 0; half < 2; half++) {
                const int r  = m0 + wm * 64 + mi * 16 + gi + half * 8;
                const int cg = n0 + wn * 32 + n8 * 8 + qi * 2;
                *reinterpret_cast<float2*>(&outp[(size_t)r * NKV + cg]) =
                    make_float2(acc[mi][n8][2 * half], acc[mi][n8][2 * half + 1]);
            }
}

// ---------------- row softmax: raw S -> P (in place) + P hi/lo -------------
__global__ __launch_bounds__(256, 4)
void k_softmax(float* __restrict__ attn)
{
    const int wid = threadIdx.x >> 5, lane = threadIdx.x & 31;
    const size_t row = (size_t)blockIdx.x * 8 + wid;
    float* rp = attn + row * NKV;
    float4 a = reinterpret_cast<float4*>(rp)[lane];
    float4 c = reinterpret_cast<float4*>(rp)[lane + 32];
    float m = fmaxf(fmaxf(fmaxf(a.x, a.y), fmaxf(a.z, a.w)),
                    fmaxf(fmaxf(c.x, c.y), fmaxf(c.z, c.w)));
#pragma unroll
    for (int off = 16; off; off >>= 1)
        m = fmaxf(m, __shfl_xor_sync(0xFFFFFFFFu, m, off));
    a.x = __expf(a.x - m); a.y = __expf(a.y - m);
    a.z = __expf(a.z - m); a.w = __expf(a.w - m);
    c.x = __expf(c.x - m); c.y = __expf(c.y - m);
    c.z = __expf(c.z - m); c.w = __expf(c.w - m);
    float s = a.x + a.y + a.z + a.w + c.x + c.y + c.z + c.w;
#pragma unroll
    for (int off = 16; off; off >>= 1)
        s += __shfl_xor_sync(0xFFFFFFFFu, s, off);
    const float inv = 1.0f / s;
    a.x *= inv; a.y *= inv; a.z *= inv; a.w *= inv;
    c.x *= inv; c.y *= inv; c.z *= inv; c.w *= inv;
    reinterpret_cast<float4*>(rp)[lane]      = a;
    reinterpret_cast<float4*>(rp)[lane + 32] = c;

    const size_t po = row * NKV + lane * 4;
    __nv_bfloat16 h0, l0, h1, l1;
    bfsplit(a.x, h0, l0); bfsplit(a.y, h1, l1);
    *reinterpret_cast<__nv_bfloat162*>(&g_Ph[po])     = __halves2bfloat162(h0, h1);
    *reinterpret_cast<__nv_bfloat162*>(&g_Pl[po])     = __halves2bfloat162(l0, l1);
    bfsplit(a.z, h0, l0); bfsplit(a.w, h1, l1);
    *reinterpret_cast<__nv_bfloat162*>(&g_Ph[po + 2]) = __halves2bfloat162(h0, h1);
    *reinterpret_cast<__nv_bfloat162*>(&g_Pl[po + 2]) = __halves2bfloat162(l0, l1);
    bfsplit(c.x, h0, l0); bfsplit(c.y, h1, l1);
    *reinterpret_cast<__nv_bfloat162*>(&g_Ph[po + 128]) = __halves2bfloat162(h0, h1);
    *reinterpret_cast<__nv_bfloat162*>(&g_Pl[po + 128]) = __halves2bfloat162(l0, l1);
    bfsplit(c.z, h0, l0); bfsplit(c.w, h1, l1);
    *reinterpret_cast<__nv_bfloat162*>(&g_Ph[po + 130]) = __halves2bfloat162(h0, h1);
    *reinterpret_cast<__nv_bfloat162*>(&g_Pl[po + 130]) = __halves2bfloat162(l0, l1);
}

// ---------------- O = P @ V (batched, M128 x N64 x K256, hi/lo) ------------
#define OA_B   8192                 // A tile: 128 x 32 bf16
#define OB_B   4096                 // B tile:  64 x 32 bf16
#define OBUF_B (2 * OA_B + 2 * OB_B)

__global__ __launch_bounds__(256, 1)
void o_gemm()
{
    extern __shared__ char smem[];
    const uint32_t sb = smem_u32(smem);
    const int tid = threadIdx.x, wid = tid >> 5, lane = tid & 31;
    const int m0 = blockIdx.x * 128, bh = blockIdx.y;
    const int b = bh / HEADS, h = bh - b * HEADS;
    const int wm = wid & 3, wn = wid >> 2;           // warp tile (wm*32, wn*32)

    const char* gA[2] = {
        (const char*)(g_Ph + ((size_t)bh * NMM + m0) * NKV),
        (const char*)(g_Pl + ((size_t)bh * NMM + m0) * NKV) };
    const char* gB[2] = {
        (const char*)(g_VTh + (size_t)bh * HD * NKV),
        (const char*)(g_VTl + (size_t)bh * HD * NKV) };

    const int ck0 = tid, ck1 = tid + 256;
    auto issue = [&](int it) {
        const int kb = it * 64;
        const uint32_t bufb = sb + (uint32_t)(it & 1) * OBUF_B;
#pragma unroll
        for (int t = 0; t < 2; t++) {                // A hi/lo: 2 chunks each
            { const int row = ck0 >> 2, c16 = ck0 & 3;
              cp_async16(bufb + t * OA_B + sw_off(row, c16),
                         gA[t] + (size_t)row * 512 + kb + c16 * 16); }
            { const int row = ck1 >> 2, c16 = ck1 & 3;
              cp_async16(bufb + t * OA_B + sw_off(row, c16),
                         gA[t] + (size_t)row * 512 + kb + c16 * 16); }
        }
        if (tid < 256) {                             // B hi/lo: 1 chunk each
            const int row = tid >> 2, c16 = tid & 3; // rows 0..63
#pragma unroll
            for (int t = 0; t < 2; t++)
                cp_async16(bufb + 2 * OA_B + t * OB_B + sw_off(row, c16),
                           gB[t] + (size_t)row * 512 + kb + c16 * 16);
        }
        cp_commit();
    };

    float acc[2][4][4];
#pragma unroll
    for (int i = 0; i < 2; i++)
#pragma unroll
        for (int j = 0; j < 4; j++)
#pragma unroll
            for (int r = 0; r < 4; r++) acc[i][j][r] = 0.f;

    const int matA = lane >> 3, wiA = lane & 7;
    const int a_moff = ((matA & 1) << 3) + wiA;
    const int a_ksel = matA >> 1;
    const int b_noff = ((matA >> 1) << 3) + wiA;
    const int b_ksel = matA & 1;

    issue(0);
    const int NITER = NKV / 32;                      // 8
    for (int it = 0; it < NITER; it++) {
        if (it + 1 < NITER) { issue(it + 1); cp_wait<1>(); }
        else                 cp_wait<0>();
        __syncthreads();
        const uint32_t bufb = sb + (uint32_t)(it & 1) * OBUF_B;
        const uint32_t sAh = bufb, sAl = bufb + OA_B;
        const uint32_t sBh = bufb + 2 * OA_B, sBl = bufb + 2 * OA_B + OB_B;
#pragma unroll
        for (int kk = 0; kk < 2; kk++) {
            uint32_t ah[2][4], al[2][4], bh[2][4], bl[2][4];
#pragma unroll
            for (int mi = 0; mi < 2; mi++) {
                const int row = wm * 32 + mi * 16 + a_moff;
                const uint32_t o = sw_off(row, kk * 2 + a_ksel);
                ldmatrix_x4(ah[mi][0], ah[mi][1], ah[mi][2], ah[mi][3], sAh + o);
                ldmatrix_x4(al[mi][0], al[mi][1], al[mi][2], al[mi][3], sAl + o);
            }
#pragma unroll
            for (int ni = 0; ni < 2; ni++) {
                const int row = wn * 32 + ni * 16 + b_noff;
                const uint32_t o = sw_off(row, kk * 2 + b_ksel);
                ldmatrix_x4(bh[ni][0], bh[ni][1], bh[ni][2], bh[ni][3], sBh + o);
                ldmatrix_x4(bl[ni][0], bl[ni][1], bl[ni][2], bl[ni][3], sBl + o);
            }
#pragma unroll
            for (int mi = 0; mi < 2; mi++)
#pragma unroll
                for (int n8 = 0; n8 < 4; n8++) {
                    const int ni = n8 >> 1, p = (n8 & 1) << 1;
                    uint32_t bfh[2] = { bh[ni][p], bh[ni][p + 1] };
                    uint32_t bfl[2] = { bl[ni][p], bl[ni][p + 1] };
                    mma_bf16(acc[mi][n8], ah[mi], bfh);
                    mma_bf16(acc[mi][n8], ah[mi], bfl);
                    mma_bf16(acc[mi][n8], al[mi], bfh);
                }
        }
        __syncthreads();
    }

    const int gi = lane >> 2, qi = lane & 3;
#pragma unroll
    for (int mi = 0; mi < 2; mi++)
#pragma unroll
        for (int n8 = 0; n8 < 4; n8++)
#pragma unroll
            for (int half = 0; half < 2; half++) {
                const int q = m0 + wm * 32 + mi * 16 + gi + half * 8;
                const int d = wn * 32 + n8 * 8 + qi * 2;
                const float vx = acc[mi][n8][2 * half], vy = acc[mi][n8][2 * half + 1];
                __nv_bfloat16 hx, lx, hy, ly;
                bfsplit(vx, hx, lx); bfsplit(vy, hy, ly);
                const size_t o = ((size_t)b * NMM + q) * DIM + h * HD + d;
                *reinterpret_cast<__nv_bfloat162*>(&g_AO_hi[o]) = __halves2bfloat162(hx, hy);
                *reinterpret_cast<__nv_bfloat162*>(&g_AO_lo[o]) = __halves2bfloat162(lx, ly);
            }
}

// ---------------------------------------------------------------------------
extern "C" void kernel_launch(void* const* d_in, const int* in_sizes, int n_in,
                              void* d_out, int out_size)
{
    const float* xmm   = (const float*)d_in[0];
    const float* xv    = (const float*)d_in[1];
    const float* xa    = (const float*)d_in[2];
    const float* Wq    = (const float*)d_in[3];
    const float* Wkv   = (const float*)d_in[4];
    const float* Wproj = (const float*)d_in[5];
    const float* bproj = (const float*)d_in[6];

    float* out  = (float*)d_out;
    float* attn = out + (size_t)BS * NMM * DIM;

    const int GEMM_SMEM  = 2 * BUF_B;   // 64 KB
    const int OGEMM_SMEM = 2 * OBUF_B;  // 48 KB
    cudaFuncSetAttribute(tc_gemm<0>, cudaFuncAttributeMaxDynamicSharedMemorySize, GEMM_SMEM);
    cudaFuncSetAttribute(tc_gemm<1>, cudaFuncAttributeMaxDynamicSharedMemorySize, GEMM_SMEM);
    cudaFuncSetAttribute(tc_gemm<2>, cudaFuncAttributeMaxDynamicSharedMemorySize, GEMM_SMEM);
    cudaFuncSetAttribute(s_gemm,     cudaFuncAttributeMaxDynamicSharedMemorySize, GEMM_SMEM);
    cudaFuncSetAttribute(o_gemm,     cudaFuncAttributeMaxDynamicSharedMemorySize, OGEMM_SMEM);

    const int nsplit = M_ROWS * DIM / 2;
    k_split<<<(nsplit + 255) / 256, 256>>>(xmm);
    k_split_gather<<<(nsplit + 255) / 256, 256>>>(xv, xa);
    k_transpose_split<0><<<dim3(DIM / 32, DIM / 32), 256>>>(Wq, DIM);
    k_transpose_split<1><<<dim3(2 * DIM / 32, DIM / 32), 256>>>(Wkv, 2 * DIM);
    k_transpose_split<2><<<dim3(DIM / 32, DIM / 32), 256>>>(Wproj, DIM);

    tc_gemm<0><<<dim3(DIM / 128, M_ROWS / 128), 256, GEMM_SMEM>>>(nullptr, nullptr);
    tc_gemm<1><<<dim3(2 * DIM / 128, M_ROWS / 128), 256, GEMM_SMEM>>>(nullptr, nullptr);

    s_gemm<<<dim3(NKV / 128, NMM / 128, BS * HEADS), 256, GEMM_SMEM>>>(attn);
    k_softmax<<<BS * HEADS * NMM / 8, 256>>>(attn);
    o_gemm<<<dim3(NMM / 128, BS * HEADS), 256, OGEMM_SMEM>>>();

    tc_gemm<2><<<dim3(DIM / 128, M_ROWS / 128), 256, GEMM_SMEM>>>(bproj, out);
}

// round 8
// speedup vs baseline: 2.7251x; 1.0413x over previous
#include <cuda_runtime.h>
#include <cuda_bf16.h>
#include <math.h>
#include <stdint.h>

#define DIM   768
#define HEADS 12
#define HD    64
#define BS    32
#define NMM   256
#define NV    196
#define NA    60
#define NKV   256
#define M_ROWS (BS * NMM)       // 8192

// ---------------- scratch (device globals; no cudaMalloc allowed) ----------
__device__ __align__(16) __nv_bfloat16 g_Qh[BS * HEADS * NMM * HD];  // [b,h,q,d] (pre-scaled)
__device__ __align__(16) __nv_bfloat16 g_Ql[BS * HEADS * NMM * HD];
__device__ __align__(16) __nv_bfloat16 g_Kh[BS * HEADS * NKV * HD];  // [b,h,k,d]
__device__ __align__(16) __nv_bfloat16 g_Kl[BS * HEADS * NKV * HD];
__device__ __align__(16) __nv_bfloat16 g_VTh[BS * HEADS * HD * NKV]; // [b,h,d,k]
__device__ __align__(16) __nv_bfloat16 g_VTl[BS * HEADS * HD * NKV];

__device__ __align__(16) __nv_bfloat16 g_Amm_hi [M_ROWS * DIM];
__device__ __align__(16) __nv_bfloat16 g_Amm_lo [M_ROWS * DIM];
__device__ __align__(16) __nv_bfloat16 g_Asrc_hi[M_ROWS * DIM];
__device__ __align__(16) __nv_bfloat16 g_Asrc_lo[M_ROWS * DIM];
__device__ __align__(16) __nv_bfloat16 g_AO_hi  [M_ROWS * DIM];
__device__ __align__(16) __nv_bfloat16 g_AO_lo  [M_ROWS * DIM];
__device__ __align__(16) __nv_bfloat16 g_WqT_hi [DIM * DIM];      // [n][k]
__device__ __align__(16) __nv_bfloat16 g_WqT_lo [DIM * DIM];
__device__ __align__(16) __nv_bfloat16 g_WkvT_hi[2 * DIM * DIM];
__device__ __align__(16) __nv_bfloat16 g_WkvT_lo[2 * DIM * DIM];
__device__ __align__(16) __nv_bfloat16 g_WpT_hi [DIM * DIM];
__device__ __align__(16) __nv_bfloat16 g_WpT_lo [DIM * DIM];

// ---------------- PTX helpers (plain-sm_103-legal) -------------------------
__device__ __forceinline__ uint32_t smem_u32(const void* p) {
    uint32_t a;
    asm("{ .reg .u64 t; cvta.to.shared.u64 t, %1; cvt.u32.u64 %0, t; }" : "=r"(a) : "l"(p));
    return a;
}
__device__ __forceinline__ void cp_async16(uint32_t dst, const void* src) {
    asm volatile("cp.async.cg.shared.global [%0], [%1], 16;" :: "r"(dst), "l"(src));
}
__device__ __forceinline__ void cp_commit() {
    asm volatile("cp.async.commit_group;" ::: "memory");
}
template <int N>
__device__ __forceinline__ void cp_wait() {
    asm volatile("cp.async.wait_group %0;" :: "n"(N) : "memory");
}
__device__ __forceinline__ void ldmatrix_x4(uint32_t& r0, uint32_t& r1, uint32_t& r2,
                                            uint32_t& r3, uint32_t addr) {
    asm volatile("ldmatrix.sync.aligned.m8n8.x4.shared.b16 {%0,%1,%2,%3}, [%4];"
                 : "=r"(r0), "=r"(r1), "=r"(r2), "=r"(r3) : "r"(addr));
}
__device__ __forceinline__ void mma_bf16(float* c, const uint32_t* a, const uint32_t* b) {
    asm volatile(
        "mma.sync.aligned.m16n8k16.row.col.f32.bf16.bf16.f32 "
        "{%0,%1,%2,%3}, {%4,%5,%6,%7}, {%8,%9}, {%0,%1,%2,%3};"
        : "+f"(c[0]), "+f"(c[1]), "+f"(c[2]), "+f"(c[3])
        : "r"(a[0]), "r"(a[1]), "r"(a[2]), "r"(a[3]), "r"(b[0]), "r"(b[1]));
}
__device__ __forceinline__ void bfsplit(float x, __nv_bfloat16& hi, __nv_bfloat16& lo) {
    hi = __float2bfloat16(x);
    lo = __float2bfloat16(x - __bfloat162float(hi));
}
__device__ __forceinline__ uint32_t packbf(float x, float y) {
    __nv_bfloat162 t = __halves2bfloat162(__float2bfloat16(x), __float2bfloat16(y));
    return *reinterpret_cast<uint32_t*>(&t);
}

// ---------------- prep kernels ---------------------------------------------
__global__ void k_split(const float* __restrict__ s) {      // xmm -> g_Amm
    const int i = blockIdx.x * 256 + threadIdx.x;
    if (i >= M_ROWS * DIM / 2) return;
    const float2 v = reinterpret_cast<const float2*>(s)[i];
    __nv_bfloat16 h0, l0, h1, l1;
    bfsplit(v.x, h0, l0); bfsplit(v.y, h1, l1);
    reinterpret_cast<__nv_bfloat162*>(g_Amm_hi)[i] = __halves2bfloat162(h0, h1);
    reinterpret_cast<__nv_bfloat162*>(g_Amm_lo)[i] = __halves2bfloat162(l0, l1);
}

__global__ void k_split_gather(const float* __restrict__ xv, const float* __restrict__ xa) {
    const int u = blockIdx.x * 256 + threadIdx.x;
    if (u >= M_ROWS * DIM / 2) return;
    const int row = u / (DIM / 2), c2 = u - row * (DIM / 2);
    const int b = row >> 8, t = row & 255;
    const float* src = (t < NV) ? xv + ((size_t)(b * NV + t)) * DIM
                                : xa + ((size_t)(b * NA + (t - NV))) * DIM;
    const float2 v = reinterpret_cast<const float2*>(src)[c2];
    __nv_bfloat16 h0, l0, h1, l1;
    bfsplit(v.x, h0, l0); bfsplit(v.y, h1, l1);
    reinterpret_cast<__nv_bfloat162*>(g_Asrc_hi)[u] = __halves2bfloat162(h0, h1);
    reinterpret_cast<__nv_bfloat162*>(g_Asrc_lo)[u] = __halves2bfloat162(l0, l1);
}

template <int WSEL>   // 0=Wq, 1=Wkv, 2=Wproj  : W [768][N] -> WT hi/lo [N][768]
__global__ void k_transpose_split(const float* __restrict__ W, int N) {
    __shared__ float t[32][33];
    const int n0 = blockIdx.x * 32, k0 = blockIdx.y * 32;
    const int tx = threadIdx.x & 31, ty = threadIdx.x >> 5;   // 32 x 8
#pragma unroll
    for (int i = 0; i < 4; i++)
        t[ty + 8 * i][tx] = W[(size_t)(k0 + ty + 8 * i) * N + n0 + tx];
    __syncthreads();
    __nv_bfloat16* Thi = (WSEL == 0) ? g_WqT_hi : (WSEL == 1) ? g_WkvT_hi : g_WpT_hi;
    __nv_bfloat16* Tlo = (WSEL == 0) ? g_WqT_lo : (WSEL == 1) ? g_WkvT_lo : g_WpT_lo;
#pragma unroll
    for (int i = 0; i < 4; i++) {
        const float x = t[tx][ty + 8 * i];
        __nv_bfloat16 h, l;
        bfsplit(x, h, l);
        const size_t o = (size_t)(n0 + ty + 8 * i) * DIM + k0 + tx;
        Thi[o] = h; Tlo[o] = l;
    }
}

// ---------------- projection GEMMs (mma.sync, bf16 hi/lo) ------------------
#define TILE_B   8192               // one 128x32 bf16 tile, bytes
#define BUF_B    (4 * TILE_B)
__device__ __forceinline__ uint32_t sw_off(int row, int c16) {
    return (uint32_t)(row * 64 + ((c16 ^ ((row >> 1) & 3)) << 4));
}

template <int MODE>   // 0: Q-proj, 1: KV-proj, 2: O-proj
__global__ __launch_bounds__(256, 1)
void tc_gemm(const float* __restrict__ bias, float* __restrict__ C)
{
    extern __shared__ char smem[];
    const uint32_t sb = smem_u32(smem);
    const int tid = threadIdx.x, wid = tid >> 5, lane = tid & 31;
    const int m0 = blockIdx.y * 128, n0 = blockIdx.x * 128;
    const int wm = wid & 1, wn = wid >> 1;

    const __nv_bfloat16* Ahi = (MODE == 0) ? g_Amm_hi : (MODE == 1) ? g_Asrc_hi : g_AO_hi;
    const __nv_bfloat16* Alo = (MODE == 0) ? g_Amm_lo : (MODE == 1) ? g_Asrc_lo : g_AO_lo;
    const __nv_bfloat16* Bhi = (MODE == 0) ? g_WqT_hi : (MODE == 1) ? g_WkvT_hi : g_WpT_hi;
    const __nv_bfloat16* Blo = (MODE == 0) ? g_WqT_lo : (MODE == 1) ? g_WkvT_lo : g_WpT_lo;

    const char* gsrc[4] = {
        (const char*)(Ahi + (size_t)m0 * DIM), (const char*)(Alo + (size_t)m0 * DIM),
        (const char*)(Bhi + (size_t)n0 * DIM), (const char*)(Blo + (size_t)n0 * DIM) };

    const int ck0 = tid, ck1 = tid + 256;
    auto issue = [&](int it) {
        const int kb = it * 64;
        const uint32_t bufb = sb + (uint32_t)(it & 1) * BUF_B;
#pragma unroll
        for (int t = 0; t < 4; t++) {
            { const int row = ck0 >> 2, c16 = ck0 & 3;
              cp_async16(bufb + t * TILE_B + sw_off(row, c16),
                         gsrc[t] + (size_t)row * (DIM * 2) + kb + c16 * 16); }
            { const int row = ck1 >> 2, c16 = ck1 & 3;
              cp_async16(bufb + t * TILE_B + sw_off(row, c16),
                         gsrc[t] + (size_t)row * (DIM * 2) + kb + c16 * 16); }
        }
        cp_commit();
    };

    float acc[4][4][4];
#pragma unroll
    for (int i = 0; i < 4; i++)
#pragma unroll
        for (int j = 0; j < 4; j++)
#pragma unroll
            for (int r = 0; r < 4; r++) acc[i][j][r] = 0.f;

    const int matA = lane >> 3, wiA = lane & 7;
    const int a_moff = ((matA & 1) << 3) + wiA;
    const int a_ksel = matA >> 1;
    const int b_noff = ((matA >> 1) << 3) + wiA;
    const int b_ksel = matA & 1;

    issue(0);
    const int NITER = DIM / 32;                        // 24
    for (int it = 0; it < NITER; it++) {
        if (it + 1 < NITER) { issue(it + 1); cp_wait<1>(); }
        else                 cp_wait<0>();
        __syncthreads();
        const uint32_t bufb = sb + (uint32_t)(it & 1) * BUF_B;
        const uint32_t sAh = bufb, sAl = bufb + TILE_B;
        const uint32_t sBh = bufb + 2 * TILE_B, sBl = bufb + 3 * TILE_B;
#pragma unroll
        for (int kk = 0; kk < 2; kk++) {
            uint32_t ah[4][4], al[4][4], bh[2][4], bl[2][4];
#pragma unroll
            for (int mi = 0; mi < 4; mi++) {
                const int row = wm * 64 + mi * 16 + a_moff;
                const uint32_t o = sw_off(row, kk * 2 + a_ksel);
                ldmatrix_x4(ah[mi][0], ah[mi][1], ah[mi][2], ah[mi][3], sAh + o);
                ldmatrix_x4(al[mi][0], al[mi][1], al[mi][2], al[mi][3], sAl + o);
            }
#pragma unroll
            for (int ni = 0; ni < 2; ni++) {
                const int row = wn * 32 + ni * 16 + b_noff;
                const uint32_t o = sw_off(row, kk * 2 + b_ksel);
                ldmatrix_x4(bh[ni][0], bh[ni][1], bh[ni][2], bh[ni][3], sBh + o);
                ldmatrix_x4(bl[ni][0], bl[ni][1], bl[ni][2], bl[ni][3], sBl + o);
            }
#pragma unroll
            for (int mi = 0; mi < 4; mi++)
#pragma unroll
                for (int n8 = 0; n8 < 4; n8++) {
                    const int ni = n8 >> 1, p = (n8 & 1) << 1;
                    uint32_t bfh[2] = { bh[ni][p], bh[ni][p + 1] };
                    uint32_t bfl[2] = { bl[ni][p], bl[ni][p + 1] };
                    mma_bf16(acc[mi][n8], ah[mi], bfh);
                    mma_bf16(acc[mi][n8], ah[mi], bfl);
                    mma_bf16(acc[mi][n8], al[mi], bfh);
                }
        }
        __syncthreads();
    }

    const int gi = lane >> 2, qi = lane & 3;
#pragma unroll
    for (int mi = 0; mi < 4; mi++)
#pragma unroll
        for (int n8 = 0; n8 < 4; n8++)
#pragma unroll
            for (int half = 0; half < 2; half++) {
                const int r  = m0 + wm * 64 + mi * 16 + gi + half * 8;
                const int cg = n0 + wn * 32 + n8 * 8 + qi * 2;
                float2 v = make_float2(acc[mi][n8][2 * half], acc[mi][n8][2 * half + 1]);
                if (MODE == 0) {
                    v.x *= 0.125f; v.y *= 0.125f;          // fold 1/sqrt(hd), exact
                    const int b = r >> 8, q = r & 255, h = cg >> 6, d = cg & 63;
                    __nv_bfloat16 hx, lx, hy, ly;
                    bfsplit(v.x, hx, lx); bfsplit(v.y, hy, ly);
                    const size_t o = (((size_t)b * HEADS + h) * NMM + q) * HD + d;
                    *reinterpret_cast<__nv_bfloat162*>(&g_Qh[o]) = __halves2bfloat162(hx, hy);
                    *reinterpret_cast<__nv_bfloat162*>(&g_Ql[o]) = __halves2bfloat162(lx, ly);
                } else if (MODE == 1) {
                    const int b = r >> 8, t = r & 255;
                    __nv_bfloat16 hx, lx, hy, ly;
                    bfsplit(v.x, hx, lx); bfsplit(v.y, hy, ly);
                    if (cg < DIM) {
                        const int h = cg >> 6, d = cg & 63;
                        const size_t o = (((size_t)b * HEADS + h) * NKV + t) * HD + d;
                        *reinterpret_cast<__nv_bfloat162*>(&g_Kh[o]) = __halves2bfloat162(hx, hy);
                        *reinterpret_cast<__nv_bfloat162*>(&g_Kl[o]) = __halves2bfloat162(lx, ly);
                    } else {
                        const int c2 = cg - DIM, h = c2 >> 6, d = c2 & 63;
                        const size_t vb = ((size_t)b * HEADS + h) * HD;
                        g_VTh[(vb + d) * NKV + t] = hx; g_VTh[(vb + d + 1) * NKV + t] = hy;
                        g_VTl[(vb + d) * NKV + t] = lx; g_VTl[(vb + d + 1) * NKV + t] = ly;
                    }
                } else {
                    v.x += bias[cg]; v.y += bias[cg + 1];
                    *reinterpret_cast<float2*>(&C[(size_t)r * DIM + cg]) = v;
                }
            }
}

// ---------------- fused attention ------------------------------------------
// One CTA per (64-query tile, bh). smem: K(64K, reused as P) | Q(16K) | VT(64K) | red(2K)
// S = Q*K^T (hi/lo 3-pass), row softmax in regs (+smem cross-warp reduce),
// attn written fp32, P -> smem bf16 hi/lo, O = P*V (3-pass) -> g_AO hi/lo.
#define FA_KB   0
#define FA_QB   65536
#define FA_VB   81920
#define FA_RED  147456
#define FA_SMEM (FA_RED + 2048)

__global__ __launch_bounds__(256, 1)
void fattn(float* __restrict__ attn)
{
    extern __shared__ char smem[];
    const uint32_t sb = smem_u32(smem);
    const int tid = threadIdx.x, wid = tid >> 5, lane = tid & 31;
    const int m0 = blockIdx.x * 64, bh = blockIdx.y;
    const int b = bh / HEADS, h = bh - b * HEADS;
    const int wm = wid & 1, wn = wid >> 1;            // S phase: 2(m) x 4(n)

    const int matA = lane >> 3, wiA = lane & 7;
    const int a_moff = ((matA & 1) << 3) + wiA;
    const int a_ksel = matA >> 1;
    const int b_noff = ((matA >> 1) << 3) + wiA;
    const int b_ksel = matA & 1;
    const int gi = lane >> 2, qi = lane & 3;

    const char* KH = (const char*)(g_Kh + (size_t)bh * NKV * HD);
    const char* KL = (const char*)(g_Kl + (size_t)bh * NKV * HD);
    const char* QH = (const char*)(g_Qh + ((size_t)bh * NMM + m0) * HD);
    const char* QL = (const char*)(g_Ql + ((size_t)bh * NMM + m0) * HD);
    const char* VH = (const char*)(g_VTh + (size_t)bh * HD * NKV);
    const char* VL = (const char*)(g_VTl + (size_t)bh * HD * NKV);

    // group 0: K + Q
#pragma unroll
    for (int u = 0; u < 8; u++) {
        const int i = u * 256 + tid;                 // 0..2047
        const int t = i >> 3, c = (i >> 2) & 1, c16 = i & 3;
        cp_async16(sb + FA_KB + c * 16384 + sw_off(t, c16), KH + t * 128 + c * 64 + c16 * 16);
        cp_async16(sb + FA_KB + 32768 + c * 16384 + sw_off(t, c16), KL + t * 128 + c * 64 + c16 * 16);
    }
#pragma unroll
    for (int u = 0; u < 2; u++) {
        const int i = u * 256 + tid;                 // 0..511
        const int r = i >> 3, c = (i >> 2) & 1, c16 = i & 3;
        cp_async16(sb + FA_QB + c * 4096 + sw_off(r, c16), QH + r * 128 + c * 64 + c16 * 16);
        cp_async16(sb + FA_QB + 8192 + c * 4096 + sw_off(r, c16), QL + r * 128 + c * 64 + c16 * 16);
    }
    cp_commit();
    // group 1: VT (consumed only in O phase)
#pragma unroll
    for (int u = 0; u < 8; u++) {
        const int i = u * 256 + tid;                 // 0..2047
        const int d = i >> 5, ch = (i >> 2) & 7, c16 = i & 3;
        cp_async16(sb + FA_VB + ch * 4096 + sw_off(d, c16), VH + d * 512 + ch * 64 + c16 * 16);
        cp_async16(sb + FA_VB + 32768 + ch * 4096 + sw_off(d, c16), VL + d * 512 + ch * 64 + c16 * 16);
    }
    cp_commit();
    cp_wait<1>();
    __syncthreads();

    // ---- S = Q*K^T ----
    float acc[2][8][4];
#pragma unroll
    for (int i = 0; i < 2; i++)
#pragma unroll
        for (int j = 0; j < 8; j++)
#pragma unroll
            for (int r = 0; r < 4; r++) acc[i][j][r] = 0.f;

#pragma unroll
    for (int ch = 0; ch < 2; ch++)
#pragma unroll
        for (int kk = 0; kk < 2; kk++) {
            uint32_t ah[2][4], al[2][4], bhv[4][4], blv[4][4];
#pragma unroll
            for (int mi = 0; mi < 2; mi++) {
                const int row = wm * 32 + mi * 16 + a_moff;
                const uint32_t o = FA_QB + ch * 4096 + sw_off(row, kk * 2 + a_ksel);
                ldmatrix_x4(ah[mi][0], ah[mi][1], ah[mi][2], ah[mi][3], sb + o);
                ldmatrix_x4(al[mi][0], al[mi][1], al[mi][2], al[mi][3], sb + o + 8192);
            }
#pragma unroll
            for (int ni = 0; ni < 4; ni++) {
                const int row = wn * 64 + ni * 16 + b_noff;
                const uint32_t o = FA_KB + ch * 16384 + sw_off(row, kk * 2 + b_ksel);
                ldmatrix_x4(bhv[ni][0], bhv[ni][1], bhv[ni][2], bhv[ni][3], sb + o);
                ldmatrix_x4(blv[ni][0], blv[ni][1], blv[ni][2], blv[ni][3], sb + o + 32768);
            }
#pragma unroll
            for (int mi = 0; mi < 2; mi++)
#pragma unroll
                for (int n8 = 0; n8 < 8; n8++) {
                    const int ni = n8 >> 1, p = (n8 & 1) << 1;
                    uint32_t bfh[2] = { bhv[ni][p], bhv[ni][p + 1] };
                    uint32_t bfl[2] = { blv[ni][p], blv[ni][p + 1] };
                    mma_bf16(acc[mi][n8], ah[mi], bfh);
                    mma_bf16(acc[mi][n8], ah[mi], bfl);
                    mma_bf16(acc[mi][n8], al[mi], bfh);
                }
        }
    __syncthreads();    // all K/Q smem reads done

    // ---- row softmax (rows span 4 n-warps) ----
    float* redm = (float*)(smem + FA_RED);          // [4][64]
    float* reds = (float*)(smem + FA_RED + 1024);
    float mfin[2][2], inv[2][2];
#pragma unroll
    for (int mi = 0; mi < 2; mi++)
#pragma unroll
        for (int hf = 0; hf < 2; hf++) {
            float m = -INFINITY;
#pragma unroll
            for (int n8 = 0; n8 < 8; n8++)
                m = fmaxf(m, fmaxf(acc[mi][n8][2 * hf], acc[mi][n8][2 * hf + 1]));
            m = fmaxf(m, __shfl_xor_sync(0xFFFFFFFFu, m, 1));
            m = fmaxf(m, __shfl_xor_sync(0xFFFFFFFFu, m, 2));
            if (qi == 0) redm[wn * 64 + wm * 32 + mi * 16 + gi + hf * 8] = m;
        }
    __syncthreads();
#pragma unroll
    for (int mi = 0; mi < 2; mi++)
#pragma unroll
        for (int hf = 0; hf < 2; hf++) {
            const int rl = wm * 32 + mi * 16 + gi + hf * 8;
            float m = fmaxf(fmaxf(redm[rl], redm[64 + rl]),
                            fmaxf(redm[128 + rl], redm[192 + rl]));
            mfin[mi][hf] = m;
            float s = 0.f;
#pragma unroll
            for (int n8 = 0; n8 < 8; n8++) {
                float e0 = __expf(acc[mi][n8][2 * hf] - m);
                float e1 = __expf(acc[mi][n8][2 * hf + 1] - m);
                acc[mi][n8][2 * hf] = e0; acc[mi][n8][2 * hf + 1] = e1;
                s += e0 + e1;
            }
            s += __shfl_xor_sync(0xFFFFFFFFu, s, 1);
            s += __shfl_xor_sync(0xFFFFFFFFu, s, 2);
            if (qi == 0) reds[wn * 64 + rl] = s;
        }
    __syncthreads();
#pragma unroll
    for (int mi = 0; mi < 2; mi++)
#pragma unroll
        for (int hf = 0; hf < 2; hf++) {
            const int rl = wm * 32 + mi * 16 + gi + hf * 8;
            inv[mi][hf] = 1.0f / (reds[rl] + reds[64 + rl] + reds[128 + rl] + reds[192 + rl]);
        }

    // ---- write attn (fp32) + P -> smem (bf16 hi/lo, overwrites K region) ----
    float* outp = attn + ((size_t)bh * NMM + m0) * NKV;
#pragma unroll
    for (int mi = 0; mi < 2; mi++)
#pragma unroll
        for (int n8 = 0; n8 < 8; n8++)
#pragma unroll
            for (int hf = 0; hf < 2; hf++) {
                const int rl = wm * 32 + mi * 16 + gi + hf * 8;
                const int col = wn * 64 + n8 * 8 + qi * 2;
                const float px = acc[mi][n8][2 * hf] * inv[mi][hf];
                const float py = acc[mi][n8][2 * hf + 1] * inv[mi][hf];
                *reinterpret_cast<float2*>(&outp[(size_t)rl * NKV + col]) = make_float2(px, py);
                __nv_bfloat16 hx, lx, hy, ly;
                bfsplit(px, hx, lx); bfsplit(py, hy, ly);
                const int cc = col & 31;
                const uint32_t po = (uint32_t)((col >> 5) * 4096) + sw_off(rl, cc >> 3) + (cc & 7) * 2;
                __nv_bfloat162 hp = __halves2bfloat162(hx, hy);
                __nv_bfloat162 lp = __halves2bfloat162(lx, ly);
                *reinterpret_cast<uint32_t*>(smem + FA_KB + po) = *reinterpret_cast<uint32_t*>(&hp);
                *reinterpret_cast<uint32_t*>(smem + FA_KB + 32768 + po) = *reinterpret_cast<uint32_t*>(&lp);
            }
    cp_wait<0>();
    __syncthreads();    // P visible, VT loaded

    // ---- O = P @ V : 8 warps as 4(m) x 2(n), warp tile 16q x 32d, K=256 ----
    const int om = wid & 3, on = wid >> 2;
    float oacc[4][4];
#pragma unroll
    for (int j = 0; j < 4; j++)
#pragma unroll
        for (int r = 0; r < 4; r++) oacc[j][r] = 0.f;

#pragma unroll
    for (int ch = 0; ch < 8; ch++)
#pragma unroll
        for (int kk = 0; kk < 2; kk++) {
            uint32_t pa[4], pl[4], vbh[2][4], vbl[2][4];
            {
                const int row = om * 16 + a_moff;
                const uint32_t o = FA_KB + ch * 4096 + sw_off(row, kk * 2 + a_ksel);
                ldmatrix_x4(pa[0], pa[1], pa[2], pa[3], sb + o);
                ldmatrix_x4(pl[0], pl[1], pl[2], pl[3], sb + o + 32768);
            }
#pragma unroll
            for (int ni = 0; ni < 2; ni++) {
                const int row = on * 32 + ni * 16 + b_noff;
                const uint32_t o = FA_VB + ch * 4096 + sw_off(row, kk * 2 + b_ksel);
                ldmatrix_x4(vbh[ni][0], vbh[ni][1], vbh[ni][2], vbh[ni][3], sb + o);
                ldmatrix_x4(vbl[ni][0], vbl[ni][1], vbl[ni][2], vbl[ni][3], sb + o + 32768);
            }
#pragma unroll
            for (int n8 = 0; n8 < 4; n8++) {
                const int ni = n8 >> 1, p = (n8 & 1) << 1;
                uint32_t bfh[2] = { vbh[ni][p], vbh[ni][p + 1] };
                uint32_t bfl[2] = { vbl[ni][p], vbl[ni][p + 1] };
                mma_bf16(oacc[n8], pa, bfh);
                mma_bf16(oacc[n8], pa, bfl);
                mma_bf16(oacc[n8], pl, bfh);
            }
        }

#pragma unroll
    for (int n8 = 0; n8 < 4; n8++)
#pragma unroll
        for (int hf = 0; hf < 2; hf++) {
            const int q = m0 + om * 16 + gi + hf * 8;
            const int d = on * 32 + n8 * 8 + qi * 2;
            __nv_bfloat16 hx, lx, hy, ly;
            bfsplit(oacc[n8][2 * hf], hx, lx); bfsplit(oacc[n8][2 * hf + 1], hy, ly);
            const size_t o = ((size_t)b * NMM + q) * DIM + h * HD + d;
            *reinterpret_cast<__nv_bfloat162*>(&g_AO_hi[o]) = __halves2bfloat162(hx, hy);
            *reinterpret_cast<__nv_bfloat162*>(&g_AO_lo[o]) = __halves2bfloat162(lx, ly);
        }
}

// ---------------------------------------------------------------------------
extern "C" void kernel_launch(void* const* d_in, const int* in_sizes, int n_in,
                              void* d_out, int out_size)
{
    const float* xmm   = (const float*)d_in[0];
    const float* xv    = (const float*)d_in[1];
    const float* xa    = (const float*)d_in[2];
    const float* Wq    = (const float*)d_in[3];
    const float* Wkv   = (const float*)d_in[4];
    const float* Wproj = (const float*)d_in[5];
    const float* bproj = (const float*)d_in[6];

    float* out  = (float*)d_out;
    float* attn = out + (size_t)BS * NMM * DIM;

    const int GEMM_SMEM = 2 * BUF_B;   // 64 KB
    cudaFuncSetAttribute(tc_gemm<0>, cudaFuncAttributeMaxDynamicSharedMemorySize, GEMM_SMEM);
    cudaFuncSetAttribute(tc_gemm<1>, cudaFuncAttributeMaxDynamicSharedMemorySize, GEMM_SMEM);
    cudaFuncSetAttribute(tc_gemm<2>, cudaFuncAttributeMaxDynamicSharedMemorySize, GEMM_SMEM);
    cudaFuncSetAttribute(fattn,      cudaFuncAttributeMaxDynamicSharedMemorySize, FA_SMEM);

    const int nsplit = M_ROWS * DIM / 2;
    k_split<<<(nsplit + 255) / 256, 256>>>(xmm);
    k_split_gather<<<(nsplit + 255) / 256, 256>>>(xv, xa);
    k_transpose_split<0><<<dim3(DIM / 32, DIM / 32), 256>>>(Wq, DIM);
    k_transpose_split<1><<<dim3(2 * DIM / 32, DIM / 32), 256>>>(Wkv, 2 * DIM);
    k_transpose_split<2><<<dim3(DIM / 32, DIM / 32), 256>>>(Wproj, DIM);

    tc_gemm<0><<<dim3(DIM / 128, M_ROWS / 128), 256, GEMM_SMEM>>>(nullptr, nullptr);
    tc_gemm<1><<<dim3(2 * DIM / 128, M_ROWS / 128), 256, GEMM_SMEM>>>(nullptr, nullptr);

    fattn<<<dim3(NMM / 64, BS * HEADS), 256, FA_SMEM>>>(attn);

    tc_gemm<2><<<dim3(DIM / 128, M_ROWS / 128), 256, GEMM_SMEM>>>(bproj, out);
}